// round 7
// baseline (speedup 1.0000x reference)
#include <cuda_runtime.h>

// ---------------------------------------------------------------------------
// VoxelBackBone8x decoder: 8 x (masked 27-tap gather conv -> BN -> ReLU)
// fp32, f32x2 packed FMA (sm_103a), smem-tiled gather-GEMM, fused BN stats.
// ---------------------------------------------------------------------------

#define ROWS 128
#define NT   256
#define FSTR 132          // featT row stride (floats): 16B-aligned rows

#define MAXN 110000
__device__ float g_bufA[MAXN * 64];
__device__ float g_bufB[MAXN * 64];
__device__ float g_sum[8 * 64];
__device__ float g_sq [8 * 64];

__device__ __forceinline__ unsigned long long pack2(float lo, float hi) {
    return ((unsigned long long)__float_as_uint(hi) << 32) |
           (unsigned long long)__float_as_uint(lo);
}
__device__ __forceinline__ float lo2(unsigned long long v) { return __uint_as_float((unsigned)v); }
__device__ __forceinline__ float hi2(unsigned long long v) { return __uint_as_float((unsigned)(v >> 32)); }
__device__ __forceinline__ void ffma2(unsigned long long& d, unsigned long long a,
                                      unsigned long long b) {
    asm("fma.rn.f32x2 %0, %1, %2, %0;" : "+l"(d) : "l"(a), "l"(b));
}

__global__ void zero_stats_kernel() {
    for (int i = threadIdx.x; i < 8 * 64; i += blockDim.x) {
        g_sum[i] = 0.f;
        g_sq[i]  = 0.f;
    }
}

// ---------------------------------------------------------------------------
// Tiled gather-conv: out rows N, gathers fin rows via nbr (N,27), W (27,CI,CO).
// Also accumulates per-channel sum / sumsq into sumP/sqP.
// ---------------------------------------------------------------------------
template <int CI, int CO>
__global__ void __launch_bounds__(NT) conv_kernel(
    const float* __restrict__ fin, const int* __restrict__ nbr,
    const float* __restrict__ W, float* __restrict__ fout,
    float* __restrict__ sumP, float* __restrict__ sqP, int N)
{
    constexpr int TN = 4;
    constexpr int BX = CO / TN;       // threads along columns
    constexpr int BY = NT / BX;       // threads along rows
    constexpr int TM = ROWS / BY;     // rows per thread (8 / 4 / 2)
    constexpr int NP = TM / 2;        // row-pairs per thread

    extern __shared__ float smem[];
    float* featT = smem;                          // CI * FSTR
    float* Wt    = featT + CI * FSTR;             // CI * CO
    float* ssum  = Wt + CI * CO;                  // CO
    float* ssq   = ssum + CO;                     // CO
    int*   jsm   = (int*)(ssq + CO);              // ROWS * 27

    const int tid  = threadIdx.x;
    const int row0 = blockIdx.x * ROWS;
    int nvalid = N - row0;
    if (nvalid > ROWS) nvalid = ROWS;

    for (int i = tid; i < 2 * CO; i += NT) ssum[i] = 0.f;
    for (int i = tid; i < ROWS * 27; i += NT)
        jsm[i] = (i < nvalid * 27) ? nbr[row0 * 27 + i] : -1;

    unsigned long long acc[NP][TN];
#pragma unroll
    for (int p = 0; p < NP; p++)
#pragma unroll
        for (int c = 0; c < TN; c++) acc[p][c] = 0ull;

    const int gr_row = tid & (ROWS - 1);   // gather: one lane per row
    const int ghalf  = tid >> 7;
    constexpr int CPT = CI / 8;            // float4 chunks per gather thread

    const int tx = tid % BX, ty = tid / BX;
    const int c0 = tx * TN, r0 = ty * TM;

    for (int t = 0; t < 27; t++) {
        __syncthreads();
        // stage W[t] into smem
        const float4* Wg = reinterpret_cast<const float4*>(W + t * CI * CO);
        for (int i = tid; i < CI * CO / 4; i += NT)
            reinterpret_cast<float4*>(Wt)[i] = Wg[i];
        // gather features, transposed featT[k][r]; lanes write consecutive r
        {
            const int j = jsm[gr_row * 27 + t];
#pragma unroll
            for (int cc = 0; cc < CPT; cc++) {
                const int ch = ghalf * CPT + cc;
                float4 v = make_float4(0.f, 0.f, 0.f, 0.f);
                if (j >= 0)
                    v = reinterpret_cast<const float4*>(fin)[j * (CI / 4) + ch];
                const int k = ch * 4;
                featT[(k + 0) * FSTR + gr_row] = v.x;
                featT[(k + 1) * FSTR + gr_row] = v.y;
                featT[(k + 2) * FSTR + gr_row] = v.z;
                featT[(k + 3) * FSTR + gr_row] = v.w;
            }
        }
        __syncthreads();
        // GEMM: acc += featT[:, rows]^T * Wt
#pragma unroll 4
        for (int k = 0; k < CI; k++) {
            unsigned long long ap[NP];
            const float* fr = &featT[k * FSTR + r0];
            if constexpr (TM == 8) {
                float4 f0 = *reinterpret_cast<const float4*>(fr);
                float4 f1 = *reinterpret_cast<const float4*>(fr + 4);
                ap[0] = pack2(f0.x, f0.y); ap[1] = pack2(f0.z, f0.w);
                ap[2] = pack2(f1.x, f1.y); ap[3] = pack2(f1.z, f1.w);
            } else if constexpr (TM == 4) {
                float4 f0 = *reinterpret_cast<const float4*>(fr);
                ap[0] = pack2(f0.x, f0.y); ap[1] = pack2(f0.z, f0.w);
            } else {
                float2 f0 = *reinterpret_cast<const float2*>(fr);
                ap[0] = pack2(f0.x, f0.y);
            }
            float4 wv = *reinterpret_cast<const float4*>(&Wt[k * CO + c0]);
            unsigned long long bw[TN] = {pack2(wv.x, wv.x), pack2(wv.y, wv.y),
                                         pack2(wv.z, wv.z), pack2(wv.w, wv.w)};
#pragma unroll
            for (int p = 0; p < NP; p++)
#pragma unroll
                for (int c = 0; c < TN; c++) ffma2(acc[p][c], ap[p], bw[c]);
        }
    }

    // write y and accumulate BN stats
    float psum[TN] = {0.f, 0.f, 0.f, 0.f};
    float psq [TN] = {0.f, 0.f, 0.f, 0.f};
#pragma unroll
    for (int p = 0; p < NP; p++) {
#pragma unroll
        for (int e = 0; e < 2; e++) {
            const int rr = r0 + 2 * p + e;
            const int gr = row0 + rr;
            if (gr < N) {
                float v[TN];
#pragma unroll
                for (int c = 0; c < TN; c++)
                    v[c] = e ? hi2(acc[p][c]) : lo2(acc[p][c]);
                *reinterpret_cast<float4*>(&fout[gr * CO + c0]) =
                    make_float4(v[0], v[1], v[2], v[3]);
#pragma unroll
                for (int c = 0; c < TN; c++) {
                    psum[c] += v[c];
                    psq[c]  += v[c] * v[c];
                }
            }
        }
    }
#pragma unroll
    for (int c = 0; c < TN; c++) {
        atomicAdd(&ssum[c0 + c], psum[c]);
        atomicAdd(&ssq [c0 + c], psq[c]);
    }
    __syncthreads();
    if (tid < CO) {
        atomicAdd(&sumP[tid], ssum[tid]);
        atomicAdd(&sqP [tid], ssq[tid]);
    }
}

// ---------------------------------------------------------------------------
// Final 16 -> 3 conv (tiny compute): one thread per row.
// ---------------------------------------------------------------------------
__global__ void __launch_bounds__(256) conv_c5_kernel(
    const float* __restrict__ fin, const int* __restrict__ nbr,
    const float* __restrict__ W, float* __restrict__ fout,
    float* __restrict__ sumP, float* __restrict__ sqP, int N)
{
    __shared__ float Ws[27 * 16 * 3];
    __shared__ float ss[6];
    const int tid = threadIdx.x;
    for (int i = tid; i < 27 * 48; i += 256) Ws[i] = W[i];
    if (tid < 6) ss[tid] = 0.f;
    __syncthreads();

    const int row = blockIdx.x * 256 + tid;
    float a0 = 0.f, a1 = 0.f, a2 = 0.f;
    if (row < N) {
        for (int t = 0; t < 27; t++) {
            const int j = nbr[row * 27 + t];
            if (j >= 0) {
                const float4* fr = reinterpret_cast<const float4*>(fin + j * 16);
                float f[16];
                float4 q;
                q = fr[0]; f[0] = q.x; f[1] = q.y; f[2]  = q.z; f[3]  = q.w;
                q = fr[1]; f[4] = q.x; f[5] = q.y; f[6]  = q.z; f[7]  = q.w;
                q = fr[2]; f[8] = q.x; f[9] = q.y; f[10] = q.z; f[11] = q.w;
                q = fr[3]; f[12] = q.x; f[13] = q.y; f[14] = q.z; f[15] = q.w;
#pragma unroll
                for (int k = 0; k < 16; k++) {
                    const float* wp = &Ws[(t * 16 + k) * 3];
                    a0 += f[k] * wp[0];
                    a1 += f[k] * wp[1];
                    a2 += f[k] * wp[2];
                }
            }
        }
        fout[row * 3 + 0] = a0;
        fout[row * 3 + 1] = a1;
        fout[row * 3 + 2] = a2;
    }
    // invalid rows contribute exact zeros -> sums unchanged
    atomicAdd(&ss[0], a0); atomicAdd(&ss[1], a1); atomicAdd(&ss[2], a2);
    atomicAdd(&ss[3], a0 * a0); atomicAdd(&ss[4], a1 * a1); atomicAdd(&ss[5], a2 * a2);
    __syncthreads();
    if (tid < 3) {
        atomicAdd(&sumP[tid], ss[tid]);
        atomicAdd(&sqP [tid], ss[3 + tid]);
    }
}

// ---------------------------------------------------------------------------
// BN apply: y = (optional relu)( y * a + B ),  a = g*rsqrt(var+1e-3), B = b-mu*a
// ---------------------------------------------------------------------------
__global__ void normalize_kernel(const float* __restrict__ in, float* __restrict__ out,
                                 int N, int C, const float* __restrict__ g,
                                 const float* __restrict__ b,
                                 const float* __restrict__ sum,
                                 const float* __restrict__ sq, int relu)
{
    extern __shared__ float s[];   // [C] scale, [C] shift
    if (threadIdx.x < C) {
        const float mu  = sum[threadIdx.x] / (float)N;
        const float var = sq[threadIdx.x] / (float)N - mu * mu;
        const float a   = g[threadIdx.x] * rsqrtf(var + 1e-3f);
        s[threadIdx.x]     = a;
        s[C + threadIdx.x] = b[threadIdx.x] - mu * a;
    }
    __syncthreads();
    const int total  = N * C;
    const int stride = gridDim.x * blockDim.x;
    for (int i = blockIdx.x * blockDim.x + threadIdx.x; i < total; i += stride) {
        const int c = i % C;
        float v = in[i] * s[c] + s[C + c];
        if (relu) v = fmaxf(v, 0.f);
        out[i] = v;
    }
}

// ---------------------------------------------------------------------------

static inline int conv_smem(int CI, int CO) {
    return (CI * FSTR + CI * CO + 2 * CO) * 4 + ROWS * 27 * 4;
}

extern "C" void kernel_launch(void* const* d_in, const int* in_sizes, int n_in,
                              void* d_out, int out_size)
{
    (void)n_in;
    // Detect input ordering: signature order (x first) vs dict order (x at 7).
    const long s0 = in_sizes[0], s1 = in_sizes[1];
    const bool sig = (s0 % 64 == 0) && (s1 % 27 == 0) && (s0 / 64 == s1 / 27);

    const float* x;
    const int* NB[7];   // nbr4, inv43, nbr3, inv32, nbr2, inv21, nbr1
    if (sig) {
        x = (const float*)d_in[0];
        for (int i = 0; i < 7; i++) NB[i] = (const int*)d_in[1 + i];
    } else {
        x = (const float*)d_in[7];
        for (int i = 0; i < 7; i++) NB[i] = (const int*)d_in[i];
    }
    const int n4 = (sig ? in_sizes[0] : in_sizes[7]) / 64;
    const int n3 = (sig ? in_sizes[2] : in_sizes[1]) / 27;  // inv43 rows
    const int n2 = (sig ? in_sizes[4] : in_sizes[3]) / 27;  // inv32 rows
    const int n1 = out_size / 3;

    const float *Wp[8], *Gp[8], *Bp[8];
    for (int i = 0; i < 8; i++) {
        Wp[i] = (const float*)d_in[8 + 3 * i];
        Gp[i] = (const float*)d_in[9 + 3 * i];
        Bp[i] = (const float*)d_in[10 + 3 * i];
    }

    float *bufA, *bufB, *sums, *sqs;
    cudaGetSymbolAddress((void**)&bufA, g_bufA);
    cudaGetSymbolAddress((void**)&bufB, g_bufB);
    cudaGetSymbolAddress((void**)&sums, g_sum);
    cudaGetSymbolAddress((void**)&sqs,  g_sq);

    const int sm6464 = conv_smem(64, 64);
    const int sm6432 = conv_smem(64, 32);
    const int sm3232 = conv_smem(32, 32);
    const int sm3216 = conv_smem(32, 16);
    const int sm1616 = conv_smem(16, 16);
    cudaFuncSetAttribute(conv_kernel<64, 64>, cudaFuncAttributeMaxDynamicSharedMemorySize, sm6464);
    cudaFuncSetAttribute(conv_kernel<64, 32>, cudaFuncAttributeMaxDynamicSharedMemorySize, sm6432);
    cudaFuncSetAttribute(conv_kernel<32, 32>, cudaFuncAttributeMaxDynamicSharedMemorySize, sm3232);
    cudaFuncSetAttribute(conv_kernel<32, 16>, cudaFuncAttributeMaxDynamicSharedMemorySize, sm3216);
    cudaFuncSetAttribute(conv_kernel<16, 16>, cudaFuncAttributeMaxDynamicSharedMemorySize, sm1616);

    auto nblk = [](int total) {
        int b = (total + 255) / 256;
        return b > 16384 ? 16384 : b;
    };
    auto grid = [](int n) { return (n + ROWS - 1) / ROWS; };

    zero_stats_kernel<<<1, 256>>>();

    // L1: m4 (x: n4 x 64 -> bufA: n4 x 64)
    conv_kernel<64, 64><<<grid(n4), NT, sm6464>>>(x, NB[0], Wp[0], bufA, sums + 0, sqs + 0, n4);
    normalize_kernel<<<nblk(n4 * 64), 256, 2 * 64 * 4>>>(bufA, bufA, n4, 64, Gp[0], Bp[0], sums + 0, sqs + 0, 1);
    // L2: i4 (bufA[n4] -> bufB: n3 x 64)
    conv_kernel<64, 64><<<grid(n3), NT, sm6464>>>(bufA, NB[1], Wp[1], bufB, sums + 64, sqs + 64, n3);
    normalize_kernel<<<nblk(n3 * 64), 256, 2 * 64 * 4>>>(bufB, bufB, n3, 64, Gp[1], Bp[1], sums + 64, sqs + 64, 1);
    // L3: m3 (bufB -> bufA: n3 x 64)
    conv_kernel<64, 64><<<grid(n3), NT, sm6464>>>(bufB, NB[2], Wp[2], bufA, sums + 128, sqs + 128, n3);
    normalize_kernel<<<nblk(n3 * 64), 256, 2 * 64 * 4>>>(bufA, bufA, n3, 64, Gp[2], Bp[2], sums + 128, sqs + 128, 1);
    // L4: i3 (bufA[n3] -> bufB: n2 x 32)
    conv_kernel<64, 32><<<grid(n2), NT, sm6432>>>(bufA, NB[3], Wp[3], bufB, sums + 192, sqs + 192, n2);
    normalize_kernel<<<nblk(n2 * 32), 256, 2 * 32 * 4>>>(bufB, bufB, n2, 32, Gp[3], Bp[3], sums + 192, sqs + 192, 1);
    // L5: m2 (bufB -> bufA: n2 x 32)
    conv_kernel<32, 32><<<grid(n2), NT, sm3232>>>(bufB, NB[4], Wp[4], bufA, sums + 256, sqs + 256, n2);
    normalize_kernel<<<nblk(n2 * 32), 256, 2 * 32 * 4>>>(bufA, bufA, n2, 32, Gp[4], Bp[4], sums + 256, sqs + 256, 1);
    // L6: i2 (bufA[n2] -> bufB: n1 x 16)
    conv_kernel<32, 16><<<grid(n1), NT, sm3216>>>(bufA, NB[5], Wp[5], bufB, sums + 320, sqs + 320, n1);
    normalize_kernel<<<nblk(n1 * 16), 256, 2 * 16 * 4>>>(bufB, bufB, n1, 16, Gp[5], Bp[5], sums + 320, sqs + 320, 1);
    // L7: m1 (bufB -> bufA: n1 x 16)
    conv_kernel<16, 16><<<grid(n1), NT, sm1616>>>(bufB, NB[6], Wp[6], bufA, sums + 384, sqs + 384, n1);
    normalize_kernel<<<nblk(n1 * 16), 256, 2 * 16 * 4>>>(bufA, bufA, n1, 16, Gp[6], Bp[6], sums + 384, sqs + 384, 1);
    // L8: c5 (bufA -> bufB: n1 x 3), BN without relu -> d_out
    conv_c5_kernel<<<(n1 + 255) / 256, 256>>>(bufA, NB[6], Wp[7], bufB, sums + 448, sqs + 448, n1);
    normalize_kernel<<<nblk(n1 * 3), 256, 2 * 3 * 4>>>(bufB, (float*)d_out, n1, 3, Gp[7], Bp[7], sums + 448, sqs + 448, 0);
}